// round 9
// baseline (speedup 1.0000x reference)
#include <cuda_runtime.h>
#include <cstdint>

#define N_ATOMS_MAX 200000
#define N_IMAGES_MAX 128

// Zero-initialized at module load. Every run restores the all-zero invariant:
//  - atom_kernel writes zeros back to each scratch row it consumes
//  - the last block re-zeros g_virial and resets g_counter
__device__ __align__(16) float g_scratch[(size_t)N_ATOMS_MAX * 12];
__device__ __align__(16) float g_virial[N_IMAGES_MAX * 12];
__device__ int g_counter;   // zero-init, reset by last block each run

__device__ __forceinline__ void red4(float* p, float a, float b, float c, float d) {
    asm volatile("red.global.add.v4.f32 [%0], {%1,%2,%3,%4};"
                 :: "l"(p), "f"(a), "f"(b), "f"(c), "f"(d) : "memory");
}

__device__ __forceinline__ void process_edge(
    float dx, float dy, float dz,
    float gx, float gy, float gz,
    int i, int j)
{
    // i endpoint: 3 force comps + 9 virial comps packed into exactly 3 v4 reds
    float* si = g_scratch + (size_t)i * 12;
    red4(si + 0, gx,      gy,      gz,      dx * gx);
    red4(si + 4, dx * gy, dx * gz, dy * gx, dy * gy);
    red4(si + 8, dy * gz, dz * gx, dz * gy, dz * gz);
    // j endpoint: force -= g
    float* sj = g_scratch + (size_t)j * 12;
    red4(sj + 0, -gx, -gy, -gz, 0.f);
}

__global__ __launch_bounds__(256) void edge_kernel(
    const float* __restrict__ edge_diff,
    const float* __restrict__ dE,
    const int* __restrict__ edge_idx,
    int n_edges)
{
    int q = blockIdx.x * blockDim.x + threadIdx.x;   // 4 edges per thread
    int base = 4 * q;
    if (base >= n_edges) return;

    if (base + 3 < n_edges) {
        const float4* diff4 = (const float4*)edge_diff;
        const float4* dE4   = (const float4*)dE;
        const int4*   idx4  = (const int4*)edge_idx;

        float4 d0 = diff4[3 * q + 0];
        float4 d1 = diff4[3 * q + 1];
        float4 d2 = diff4[3 * q + 2];
        float4 g0 = dE4[3 * q + 0];
        float4 g1 = dE4[3 * q + 1];
        float4 g2 = dE4[3 * q + 2];
        int4 i0 = idx4[2 * q + 0];
        int4 i1 = idx4[2 * q + 1];

        process_edge(d0.x, d0.y, d0.z, g0.x, g0.y, g0.z, i0.x, i0.y);
        process_edge(d0.w, d1.x, d1.y, g0.w, g1.x, g1.y, i0.z, i0.w);
        process_edge(d1.z, d1.w, d2.x, g1.z, g1.w, g2.x, i1.x, i1.y);
        process_edge(d2.y, d2.z, d2.w, g2.y, g2.z, g2.w, i1.z, i1.w);
    } else {
        for (int e = base; e < n_edges; e++) {
            process_edge(edge_diff[3 * e + 0], edge_diff[3 * e + 1], edge_diff[3 * e + 2],
                         dE[3 * e + 0], dE[3 * e + 1], dE[3 * e + 2],
                         edge_idx[2 * e + 0], edge_idx[2 * e + 1]);
        }
    }
}

// 4 atoms per thread. image_idx is sorted, so a 128-atom warp span is almost
// always image-uniform -> one butterfly + one red4-triple per 128 atoms.
__global__ __launch_bounds__(256) void atom_kernel(
    const int* __restrict__ image_idx,
    const float* __restrict__ cell,
    float* __restrict__ out,
    int n_atoms, int n_images)
{
    int t = blockIdx.x * blockDim.x + threadIdx.x;
    int a0 = 4 * t;
    const float4 z4 = make_float4(0.f, 0.f, 0.f, 0.f);

    float v[9];
#pragma unroll
    for (int k = 0; k < 9; k++) v[k] = 0.f;

    int my_img = -1;          // thread-uniform image, or -1
    bool full = (a0 + 3 < n_atoms);

    if (full) {
        int4 im = ((const int4*)image_idx)[t];
        if (im.x == im.y && im.x == im.z && im.x == im.w) my_img = im.x;

        // 12 independent LDG.128 (high MLP), then zero-restore, sum virials,
        // and emit forces as 3 aligned STG.128.
        float4* s = (float4*)(g_scratch + (size_t)a0 * 12);
        float4 r[12];
#pragma unroll
        for (int k = 0; k < 12; k++) r[k] = s[k];
#pragma unroll
        for (int k = 0; k < 12; k++) s[k] = z4;

        // per-atom layout: [fx fy fz v0][v1 v2 v3 v4][v5 v6 v7 v8]
        float4* o = (float4*)(out + (size_t)a0 * 3);
        o[0] = make_float4(r[0].x, r[0].y, r[0].z, r[3].x);
        o[1] = make_float4(r[3].y, r[3].z, r[6].x, r[6].y);
        o[2] = make_float4(r[6].z, r[9].x, r[9].y, r[9].z);

        if (my_img >= 0) {
#pragma unroll
            for (int k = 0; k < 4; k++) {
                float4 s0 = r[3 * k + 0], s1 = r[3 * k + 1], s2 = r[3 * k + 2];
                v[0] += s0.w; v[1] += s1.x; v[2] += s1.y; v[3] += s1.z;
                v[4] += s1.w; v[5] += s2.x; v[6] += s2.y; v[7] += s2.z; v[8] += s2.w;
            }
        } else {
            // mixed images within this thread: red per atom immediately
#pragma unroll
            for (int k = 0; k < 4; k++) {
                float4 s0 = r[3 * k + 0], s1 = r[3 * k + 1], s2 = r[3 * k + 2];
                int img = (k == 0) ? im.x : (k == 1) ? im.y : (k == 2) ? im.z : im.w;
                float* g = g_virial + (size_t)img * 12;
                red4(g + 0, s0.w, s1.x, s1.y, s1.z);
                red4(g + 4, s1.w, s2.x, s2.y, s2.z);
                red4(g + 8, s2.w, 0.f, 0.f, 0.f);
            }
        }
    } else {
        // tail: per-atom scalar path, red immediately
        for (int a = a0; a < n_atoms; a++) {
            float4* s = (float4*)(g_scratch + (size_t)a * 12);
            float4 s0 = s[0], s1 = s[1], s2 = s[2];
            s[0] = z4; s[1] = z4; s[2] = z4;
            out[3 * a + 0] = s0.x;
            out[3 * a + 1] = s0.y;
            out[3 * a + 2] = s0.z;
            int img = image_idx[a];
            float* g = g_virial + (size_t)img * 12;
            red4(g + 0, s0.w, s1.x, s1.y, s1.z);
            red4(g + 4, s1.w, s2.x, s2.y, s2.z);
            red4(g + 8, s2.w, 0.f, 0.f, 0.f);
        }
    }

    // Warp aggregation when the whole 128-atom span shares one image
    int lane = threadIdx.x & 31;
    int img0 = __shfl_sync(0xFFFFFFFFu, my_img, 0);
    bool warp_uniform = __all_sync(0xFFFFFFFFu, my_img == img0) && (img0 >= 0);

    if (warp_uniform) {
#pragma unroll
        for (int k = 0; k < 9; k++) {
#pragma unroll
            for (int off = 16; off > 0; off >>= 1)
                v[k] += __shfl_xor_sync(0xFFFFFFFFu, v[k], off);
        }
        if (lane == 0) {
            float* g = g_virial + (size_t)img0 * 12;
            red4(g + 0, v[0], v[1], v[2], v[3]);
            red4(g + 4, v[4], v[5], v[6], v[7]);
            red4(g + 8, v[8], 0.f, 0.f, 0.f);
        }
    } else if (my_img >= 0) {
        // thread-uniform but warp-mixed: red this thread's 4-atom partial
        float* g = g_virial + (size_t)my_img * 12;
        red4(g + 0, v[0], v[1], v[2], v[3]);
        red4(g + 4, v[4], v[5], v[6], v[7]);
        red4(g + 8, v[8], 0.f, 0.f, 0.f);
    }

    // Last-block-done: finalize virial -> out, compute stress, restore invariants
    __threadfence();
    __shared__ int is_last;
    if (threadIdx.x == 0) {
        int old = atomicAdd(&g_counter, 1);
        is_last = (old == (int)gridDim.x - 1) ? 1 : 0;
    }
    __syncthreads();
    if (is_last) {
        __threadfence();   // acquire: make all blocks' reds visible
        int i = threadIdx.x;
        if (i < n_images) {
            const float* c = cell + i * 9;
            float a0c = c[0], a1 = c[1], a2 = c[2];
            float b0 = c[3], b1 = c[4], b2 = c[5];
            float c0 = c[6], c1 = c[7], c2 = c[8];
            float x0 = b1 * c2 - b2 * c1;
            float x1 = b2 * c0 - b0 * c2;
            float x2 = b0 * c1 - b1 * c0;
            float vol = a0c * x0 + a1 * x1 + a2 * x2;
            float inv = -1.0f / vol;

            float* gv = g_virial + (size_t)i * 12;
            float* vir_out    = out + (size_t)n_atoms * 3 + (size_t)i * 9;
            float* stress_out = out + (size_t)n_atoms * 3 + (size_t)n_images * 9 + (size_t)i * 9;
            float vv[9];
#pragma unroll
            for (int k = 0; k < 9; k++) vv[k] = gv[k];
#pragma unroll
            for (int k = 0; k < 9; k++) {
                vir_out[k] = vv[k];
                stress_out[k] = vv[k] * inv;
            }
            // restore zero invariant
            float4* gv4 = (float4*)gv;
            gv4[0] = z4; gv4[1] = z4; gv4[2] = z4;
        }
        if (threadIdx.x == 0) g_counter = 0;
    }
}

extern "C" void kernel_launch(void* const* d_in, const int* in_sizes, int n_in,
                              void* d_out, int out_size)
{
    const float* edge_diff = (const float*)d_in[0];
    const float* dE        = (const float*)d_in[1];
    const float* cell      = (const float*)d_in[2];
    const int*   edge_idx  = (const int*)d_in[3];
    const int*   image_idx = (const int*)d_in[4];

    int n_edges  = in_sizes[0] / 3;
    int n_atoms  = in_sizes[4];
    int n_images = in_sizes[2] / 9;
    float* out = (float*)d_out;

    int n_quads = (n_edges + 3) / 4;
    edge_kernel<<<(n_quads + 255) / 256, 256>>>(edge_diff, dE, edge_idx, n_edges);

    int n_t = (n_atoms + 3) / 4;
    atom_kernel<<<(n_t + 255) / 256, 256>>>(image_idx, cell, out, n_atoms, n_images);
}

// round 10
// speedup vs baseline: 1.2397x; 1.2397x over previous
#include <cuda_runtime.h>
#include <cstdint>

#define N_ATOMS_MAX 200000
#define N_IMAGES_MAX 128

// Zero-initialized at module load. Every run restores the all-zero invariant:
//  - atom_kernel writes zeros back to each scratch row it consumes
//  - the last block re-zeros g_virial and resets g_counter
__device__ __align__(16) float g_scratch[(size_t)N_ATOMS_MAX * 12];
__device__ __align__(16) float g_virial[N_IMAGES_MAX * 12];
__device__ int g_counter;   // zero-init, reset by last block each run

__device__ __forceinline__ void red4(float* p, float a, float b, float c, float d) {
    asm volatile("red.global.add.v4.f32 [%0], {%1,%2,%3,%4};"
                 :: "l"(p), "f"(a), "f"(b), "f"(c), "f"(d) : "memory");
}

// Streaming (evict-first) 128-bit loads: keep read-once inputs from evicting
// the scratch RMW working set out of L2.
__device__ __forceinline__ float4 ldcs4(const float4* p) { return __ldcs(p); }
__device__ __forceinline__ int4   ldcs4i(const int4* p)  { return __ldcs(p); }

__device__ __forceinline__ void process_edge(
    float dx, float dy, float dz,
    float gx, float gy, float gz,
    int i, int j)
{
    // i endpoint: 3 force comps + 9 virial comps packed into exactly 3 v4 reds
    float* si = g_scratch + (size_t)i * 12;
    red4(si + 0, gx,      gy,      gz,      dx * gx);
    red4(si + 4, dx * gy, dx * gz, dy * gx, dy * gy);
    red4(si + 8, dy * gz, dz * gx, dz * gy, dz * gz);
    // j endpoint: force -= g
    float* sj = g_scratch + (size_t)j * 12;
    red4(sj + 0, -gx, -gy, -gz, 0.f);
}

__global__ __launch_bounds__(256) void edge_kernel(
    const float* __restrict__ edge_diff,
    const float* __restrict__ dE,
    const int* __restrict__ edge_idx,
    int n_edges)
{
    int q = blockIdx.x * blockDim.x + threadIdx.x;   // 4 edges per thread
    int base = 4 * q;
    if (base >= n_edges) return;

    if (base + 3 < n_edges) {
        const float4* diff4 = (const float4*)edge_diff;
        const float4* dE4   = (const float4*)dE;
        const int4*   idx4  = (const int4*)edge_idx;

        float4 d0 = ldcs4(diff4 + 3 * q + 0);
        float4 d1 = ldcs4(diff4 + 3 * q + 1);
        float4 d2 = ldcs4(diff4 + 3 * q + 2);
        float4 g0 = ldcs4(dE4 + 3 * q + 0);
        float4 g1 = ldcs4(dE4 + 3 * q + 1);
        float4 g2 = ldcs4(dE4 + 3 * q + 2);
        int4 i0 = ldcs4i(idx4 + 2 * q + 0);
        int4 i1 = ldcs4i(idx4 + 2 * q + 1);

        process_edge(d0.x, d0.y, d0.z, g0.x, g0.y, g0.z, i0.x, i0.y);
        process_edge(d0.w, d1.x, d1.y, g0.w, g1.x, g1.y, i0.z, i0.w);
        process_edge(d1.z, d1.w, d2.x, g1.z, g1.w, g2.x, i1.x, i1.y);
        process_edge(d2.y, d2.z, d2.w, g2.y, g2.z, g2.w, i1.z, i1.w);
    } else {
        for (int e = base; e < n_edges; e++) {
            process_edge(__ldcs(edge_diff + 3 * e + 0), __ldcs(edge_diff + 3 * e + 1),
                         __ldcs(edge_diff + 3 * e + 2),
                         __ldcs(dE + 3 * e + 0), __ldcs(dE + 3 * e + 1), __ldcs(dE + 3 * e + 2),
                         __ldcs(edge_idx + 2 * e + 0), __ldcs(edge_idx + 2 * e + 1));
        }
    }
}

// 1 atom per thread (R8 shape: 32 regs, high occupancy). image_idx sorted ->
// warp-uniform fast path: butterfly-reduce 9 virial comps, lane 0 reds once.
__global__ __launch_bounds__(256) void atom_kernel(
    const int* __restrict__ image_idx,
    const float* __restrict__ cell,
    float* __restrict__ out,
    int n_atoms, int n_images)
{
    int a = blockIdx.x * blockDim.x + threadIdx.x;
    const float4 z4 = make_float4(0.f, 0.f, 0.f, 0.f);

    int img = -1;
    float v[9];
#pragma unroll
    for (int k = 0; k < 9; k++) v[k] = 0.f;

    if (a < n_atoms) {
        float4* s = (float4*)(g_scratch + (size_t)a * 12);
        float4 s0 = s[0];  // fx fy fz v0
        float4 s1 = s[1];  // v1 v2 v3 v4
        float4 s2 = s[2];  // v5 v6 v7 v8

        // restore zero invariant for next replay
        s[0] = z4; s[1] = z4; s[2] = z4;

        out[3 * a + 0] = s0.x;
        out[3 * a + 1] = s0.y;
        out[3 * a + 2] = s0.z;

        img = image_idx[a];
        v[0] = s0.w; v[1] = s1.x; v[2] = s1.y; v[3] = s1.z;
        v[4] = s1.w; v[5] = s2.x; v[6] = s2.y; v[7] = s2.z; v[8] = s2.w;
    }

    int lane = threadIdx.x & 31;
    int img0 = __shfl_sync(0xFFFFFFFFu, img, 0);
    bool uniform = __all_sync(0xFFFFFFFFu, img == img0) && (img0 >= 0);

    if (uniform) {
#pragma unroll
        for (int k = 0; k < 9; k++) {
#pragma unroll
            for (int off = 16; off > 0; off >>= 1)
                v[k] += __shfl_xor_sync(0xFFFFFFFFu, v[k], off);
        }
        if (lane == 0) {
            float* g = g_virial + (size_t)img0 * 12;
            red4(g + 0, v[0], v[1], v[2], v[3]);
            red4(g + 4, v[4], v[5], v[6], v[7]);
            red4(g + 8, v[8], 0.f, 0.f, 0.f);
        }
    } else if (img >= 0) {
        float* g = g_virial + (size_t)img * 12;
        red4(g + 0, v[0], v[1], v[2], v[3]);
        red4(g + 4, v[4], v[5], v[6], v[7]);
        red4(g + 8, v[8], 0.f, 0.f, 0.f);
    }

    // Last-block-done: finalize virial -> out, compute stress, restore invariants
    __threadfence();
    __shared__ int is_last;
    if (threadIdx.x == 0) {
        int old = atomicAdd(&g_counter, 1);
        is_last = (old == (int)gridDim.x - 1) ? 1 : 0;
    }
    __syncthreads();
    if (is_last) {
        __threadfence();   // acquire: make all blocks' reds visible
        int i = threadIdx.x;
        if (i < n_images) {
            const float* c = cell + i * 9;
            float a0 = c[0], a1 = c[1], a2 = c[2];
            float b0 = c[3], b1 = c[4], b2 = c[5];
            float c0 = c[6], c1 = c[7], c2 = c[8];
            float x0 = b1 * c2 - b2 * c1;
            float x1 = b2 * c0 - b0 * c2;
            float x2 = b0 * c1 - b1 * c0;
            float vol = a0 * x0 + a1 * x1 + a2 * x2;
            float inv = -1.0f / vol;

            float* gv = g_virial + (size_t)i * 12;
            float* vir_out    = out + (size_t)n_atoms * 3 + (size_t)i * 9;
            float* stress_out = out + (size_t)n_atoms * 3 + (size_t)n_images * 9 + (size_t)i * 9;
            float vv[9];
#pragma unroll
            for (int k = 0; k < 9; k++) vv[k] = gv[k];
#pragma unroll
            for (int k = 0; k < 9; k++) {
                vir_out[k] = vv[k];
                stress_out[k] = vv[k] * inv;
            }
            // restore zero invariant
            float4* gv4 = (float4*)gv;
            gv4[0] = z4; gv4[1] = z4; gv4[2] = z4;
        }
        if (threadIdx.x == 0) g_counter = 0;
    }
}

extern "C" void kernel_launch(void* const* d_in, const int* in_sizes, int n_in,
                              void* d_out, int out_size)
{
    const float* edge_diff = (const float*)d_in[0];
    const float* dE        = (const float*)d_in[1];
    const float* cell      = (const float*)d_in[2];
    const int*   edge_idx  = (const int*)d_in[3];
    const int*   image_idx = (const int*)d_in[4];

    int n_edges  = in_sizes[0] / 3;
    int n_atoms  = in_sizes[4];
    int n_images = in_sizes[2] / 9;
    float* out = (float*)d_out;

    int n_quads = (n_edges + 3) / 4;
    edge_kernel<<<(n_quads + 255) / 256, 256>>>(edge_diff, dE, edge_idx, n_edges);

    atom_kernel<<<(n_atoms + 255) / 256, 256>>>(image_idx, cell, out, n_atoms, n_images);
}

// round 12
// speedup vs baseline: 1.3240x; 1.0680x over previous
#include <cuda_runtime.h>
#include <cstdint>

#define N_ATOMS_MAX 200000
#define N_IMAGES_MAX 128

// Zero-initialized at module load. Every run restores the all-zero invariant:
//  - atom_kernel writes zeros back to each scratch row it consumes
//  - finalize_kernel re-zeros g_virial
__device__ __align__(16) float g_scratch[(size_t)N_ATOMS_MAX * 12];
__device__ __align__(16) float g_virial[N_IMAGES_MAX * 12];

__device__ __forceinline__ void red4(float* p, float a, float b, float c, float d) {
    asm volatile("red.global.add.v4.f32 [%0], {%1,%2,%3,%4};"
                 :: "l"(p), "f"(a), "f"(b), "f"(c), "f"(d) : "memory");
}

__device__ __forceinline__ float4 ldcs4(const float4* p) { return __ldcs(p); }
__device__ __forceinline__ int4   ldcs4i(const int4* p)  { return __ldcs(p); }

__device__ __forceinline__ void process_edge(
    float dx, float dy, float dz,
    float gx, float gy, float gz,
    int i, int j)
{
    // i endpoint: 3 force comps + 9 virial comps packed into exactly 3 v4 reds
    float* si = g_scratch + (size_t)i * 12;
    red4(si + 0, gx,      gy,      gz,      dx * gx);
    red4(si + 4, dx * gy, dx * gz, dy * gx, dy * gy);
    red4(si + 8, dy * gz, dz * gx, dz * gy, dz * gz);
    // j endpoint: force -= g
    float* sj = g_scratch + (size_t)j * 12;
    red4(sj + 0, -gx, -gy, -gz, 0.f);
}

__global__ __launch_bounds__(256) void edge_kernel(
    const float* __restrict__ edge_diff,
    const float* __restrict__ dE,
    const int* __restrict__ edge_idx,
    int n_edges)
{
    int q = blockIdx.x * blockDim.x + threadIdx.x;   // 4 edges per thread
    int base = 4 * q;
    if (base >= n_edges) return;

    if (base + 3 < n_edges) {
        const float4* diff4 = (const float4*)edge_diff;
        const float4* dE4   = (const float4*)dE;
        const int4*   idx4  = (const int4*)edge_idx;

        float4 d0 = ldcs4(diff4 + 3 * q + 0);
        float4 d1 = ldcs4(diff4 + 3 * q + 1);
        float4 d2 = ldcs4(diff4 + 3 * q + 2);
        float4 g0 = ldcs4(dE4 + 3 * q + 0);
        float4 g1 = ldcs4(dE4 + 3 * q + 1);
        float4 g2 = ldcs4(dE4 + 3 * q + 2);
        int4 i0 = ldcs4i(idx4 + 2 * q + 0);
        int4 i1 = ldcs4i(idx4 + 2 * q + 1);

        process_edge(d0.x, d0.y, d0.z, g0.x, g0.y, g0.z, i0.x, i0.y);
        process_edge(d0.w, d1.x, d1.y, g0.w, g1.x, g1.y, i0.z, i0.w);
        process_edge(d1.z, d1.w, d2.x, g1.z, g1.w, g2.x, i1.x, i1.y);
        process_edge(d2.y, d2.z, d2.w, g2.y, g2.z, g2.w, i1.z, i1.w);
    } else {
        for (int e = base; e < n_edges; e++) {
            process_edge(__ldcs(edge_diff + 3 * e + 0), __ldcs(edge_diff + 3 * e + 1),
                         __ldcs(edge_diff + 3 * e + 2),
                         __ldcs(dE + 3 * e + 0), __ldcs(dE + 3 * e + 1), __ldcs(dE + 3 * e + 2),
                         __ldcs(edge_idx + 2 * e + 0), __ldcs(edge_idx + 2 * e + 1));
        }
    }
}

// 2 atoms per thread. No fused tail (finalize is separate -> no threadfence).
// image_idx sorted -> 64-atom warp span almost always image-uniform.
__global__ __launch_bounds__(256) void atom_kernel(
    const int* __restrict__ image_idx,
    float* __restrict__ out,
    int n_atoms)
{
    int t = blockIdx.x * blockDim.x + threadIdx.x;
    int a0 = 2 * t;
    const float4 z4 = make_float4(0.f, 0.f, 0.f, 0.f);

    int my_img = -1;      // thread-uniform image, else -1 (handled immediately)
    float v[9];
#pragma unroll
    for (int k = 0; k < 9; k++) v[k] = 0.f;

    bool active = (a0 < n_atoms);
    if (active) {
        // n_atoms is even in this problem, but guard anyway
        bool has2 = (a0 + 1 < n_atoms);

        float4* s = (float4*)(g_scratch + (size_t)a0 * 12);
        float4 r0 = s[0], r1 = s[1], r2 = s[2];
        float4 r3 = z4, r4 = z4, r5 = z4;
        if (has2) { r3 = s[3]; r4 = s[4]; r5 = s[5]; }

        s[0] = z4; s[1] = z4; s[2] = z4;
        if (has2) { s[3] = z4; s[4] = z4; s[5] = z4; }

        // forces: 6 floats, 24B, 8B-aligned -> 3 STG.64
        float2* o = (float2*)(out + (size_t)a0 * 3);
        o[0] = make_float2(r0.x, r0.y);
        if (has2) {
            o[1] = make_float2(r0.z, r3.x);
            o[2] = make_float2(r3.y, r3.z);
        } else {
            out[3 * a0 + 2] = r0.z;
        }

        int im0 = image_idx[a0];
        int im1 = has2 ? image_idx[a0 + 1] : im0;

        if (im0 == im1) {
            my_img = im0;
            v[0] = r0.w + r3.w; v[1] = r1.x + r4.x; v[2] = r1.y + r4.y;
            v[3] = r1.z + r4.z; v[4] = r1.w + r4.w; v[5] = r2.x + r5.x;
            v[6] = r2.y + r5.y; v[7] = r2.z + r5.z; v[8] = r2.w + r5.w;
        } else {
            // rare (image boundary inside pair): red both atoms immediately
            float* ga = g_virial + (size_t)im0 * 12;
            red4(ga + 0, r0.w, r1.x, r1.y, r1.z);
            red4(ga + 4, r1.w, r2.x, r2.y, r2.z);
            red4(ga + 8, r2.w, 0.f, 0.f, 0.f);
            float* gb = g_virial + (size_t)im1 * 12;
            red4(gb + 0, r3.w, r4.x, r4.y, r4.z);
            red4(gb + 4, r4.w, r5.x, r5.y, r5.z);
            red4(gb + 8, r5.w, 0.f, 0.f, 0.f);
        }
    }

    int lane = threadIdx.x & 31;
    int img0 = __shfl_sync(0xFFFFFFFFu, my_img, 0);
    bool uniform = __all_sync(0xFFFFFFFFu, my_img == img0) && (img0 >= 0);

    if (uniform) {
        // 4-stage butterfly (16,8,4,2): lane0 holds even-lane sum, lane1 odd-lane sum
#pragma unroll
        for (int k = 0; k < 9; k++) {
#pragma unroll
            for (int off = 16; off > 1; off >>= 1)
                v[k] += __shfl_xor_sync(0xFFFFFFFFu, v[k], off);
        }
        if (lane < 2) {
            float* g = g_virial + (size_t)img0 * 12;
            red4(g + 0, v[0], v[1], v[2], v[3]);
            red4(g + 4, v[4], v[5], v[6], v[7]);
            red4(g + 8, v[8], 0.f, 0.f, 0.f);
        }
    } else if (my_img >= 0) {
        float* g = g_virial + (size_t)my_img * 12;
        red4(g + 0, v[0], v[1], v[2], v[3]);
        red4(g + 4, v[4], v[5], v[6], v[7]);
        red4(g + 8, v[8], 0.f, 0.f, 0.f);
    }
}

__global__ void finalize_kernel(
    const float* __restrict__ cell,
    float* __restrict__ out,
    int n_atoms, int n_images)
{
    int i = threadIdx.x;
    if (i >= n_images) return;

    const float* c = cell + i * 9;
    float a0 = c[0], a1 = c[1], a2 = c[2];
    float b0 = c[3], b1 = c[4], b2 = c[5];
    float c0 = c[6], c1 = c[7], c2 = c[8];
    float x0 = b1 * c2 - b2 * c1;
    float x1 = b2 * c0 - b0 * c2;
    float x2 = b0 * c1 - b1 * c0;
    float vol = a0 * x0 + a1 * x1 + a2 * x2;
    float inv = -1.0f / vol;

    float* gv = g_virial + (size_t)i * 12;
    float* vir_out    = out + (size_t)n_atoms * 3 + (size_t)i * 9;
    float* stress_out = out + (size_t)n_atoms * 3 + (size_t)n_images * 9 + (size_t)i * 9;
    float vv[9];
#pragma unroll
    for (int k = 0; k < 9; k++) vv[k] = gv[k];
#pragma unroll
    for (int k = 0; k < 9; k++) {
        vir_out[k] = vv[k];
        stress_out[k] = vv[k] * inv;
    }
    // restore zero invariant
    float4* gv4 = (float4*)gv;
    gv4[0] = make_float4(0.f, 0.f, 0.f, 0.f);
    gv4[1] = make_float4(0.f, 0.f, 0.f, 0.f);
    gv4[2] = make_float4(0.f, 0.f, 0.f, 0.f);
}

extern "C" void kernel_launch(void* const* d_in, const int* in_sizes, int n_in,
                              void* d_out, int out_size)
{
    const float* edge_diff = (const float*)d_in[0];
    const float* dE        = (const float*)d_in[1];
    const float* cell      = (const float*)d_in[2];
    const int*   edge_idx  = (const int*)d_in[3];
    const int*   image_idx = (const int*)d_in[4];

    int n_edges  = in_sizes[0] / 3;
    int n_atoms  = in_sizes[4];
    int n_images = in_sizes[2] / 9;
    float* out = (float*)d_out;

    int n_quads = (n_edges + 3) / 4;
    edge_kernel<<<(n_quads + 255) / 256, 256>>>(edge_diff, dE, edge_idx, n_edges);

    int n_t = (n_atoms + 1) / 2;
    atom_kernel<<<(n_t + 255) / 256, 256>>>(image_idx, out, n_atoms);

    finalize_kernel<<<1, 128>>>(cell, out, n_atoms, n_images);
}